// round 7
// baseline (speedup 1.0000x reference)
#include <cuda_runtime.h>
#include <cstdint>

// SCM_19061064860184 — R7: cluster-2 x 512-thread register scan, inline input conv.
// Per batch: 2-CTA cluster, each CTA 512 threads owning 512 positions.
// Warp owns 32 positions + 16-halo each side (window 64, 2 slots/thread).
// s_t = convX(row t) + convS(s_{t-1}) + bias ; u lags one tick.
// Halo exchange every 8 ticks (smem + DSMEM + split cluster arrive/wait).
// No yprep: the per-row input conv is computed inline (x-halo via shfl + edge loads).

#define NN 1024
#define TT 1024
#define NTH 512
#define CLC 2
#define OWNC 512
#define NWP 16
#define HB 16
#define EXW (OWNC + 2 * HB)   // 544
#define SWR 1058              // padded stage row width (16*66=1056 -> 1058 for banks)
#define FULLM 0xffffffffu

struct alignas(16) Smem {
    float sEx[2][EXW];
    float uEx[2][EXW];
    float stage[32][SWR];
};

__device__ float g_scr[8 * NN * TT];   // phase-A output (out2, transposed layout)

__device__ __forceinline__ void conv2acc(float& o0, float& o1,
    float L2, float L1, float v0, float v1, float R0, float R1, const float tp[5])
{
    o0 = fmaf(tp[0], L2, o0); o0 = fmaf(tp[1], L1, o0); o0 = fmaf(tp[2], v0, o0);
    o0 = fmaf(tp[3], v1, o0); o0 = fmaf(tp[4], R0, o0);
    o1 = fmaf(tp[0], L1, o1); o1 = fmaf(tp[1], v0, o1); o1 = fmaf(tp[2], v1, o1);
    o1 = fmaf(tp[3], R0, o1); o1 = fmaf(tp[4], R1, o1);
}

#define HALO2(v0, v1, L2, L1, R0, R1) do {        \
    L1 = __shfl_up_sync(FULLM, v1, 1);            \
    L2 = __shfl_up_sync(FULLM, v0, 1);            \
    R0 = __shfl_down_sync(FULLM, v0, 1);          \
    R1 = __shfl_down_sync(FULLM, v1, 1);          \
} while (0)

// x-halo with warp-edge values from the extra per-thread edge load
#define XHALOE(xv, xe, L2, L1, R0, R1) do {       \
    L1 = __shfl_up_sync(FULLM, (xv).y, 1);        \
    L2 = __shfl_up_sync(FULLM, (xv).x, 1);        \
    R0 = __shfl_down_sync(FULLM, (xv).x, 1);      \
    R1 = __shfl_down_sync(FULLM, (xv).y, 1);      \
    if (lane == 0)  { L2 = (xe).x; L1 = (xe).y; } \
    if (lane == 31) { R0 = (xe).x; R1 = (xe).y; } \
} while (0)

#define CLUSTER_ARRIVE() asm volatile("barrier.cluster.arrive.aligned;" ::: "memory")
#define CLUSTER_WAIT()   asm volatile("barrier.cluster.wait.aligned;"   ::: "memory")

__device__ __forceinline__ void dsm_store2(float* lptr, int trank, float a, float b)
{
    uint32_t la = (uint32_t)__cvta_generic_to_shared(lptr);
    uint32_t ra;
    asm volatile("mapa.shared::cluster.u32 %0, %1, %2;" : "=r"(ra) : "r"(la), "r"(trank));
    asm volatile("st.shared::cluster.v2.f32 [%0], {%1, %2};"
                 :: "r"(ra), "f"(a), "f"(b) : "memory");
}

// flush 16 u-rows (indices i0..i0+15) for this CTA's 512 positions,
// transposed + reversed, float4 stores
__device__ __forceinline__ void flush16(Smem* __restrict__ sm, float* __restrict__ O,
                                        int i0, int tid, int rank)
{
    const int q  = tid & 3;
    const int rt = tid >> 2;               // 0..127
    const int cb = NN - 4 - i0 - 4 * q;
    #pragma unroll
    for (int k = 0; k < 4; ++k) {
        const int pl = rt + (k << 7);                        // local position 0..511
        const int sa = (pl >> 5) * 66 + (pl & 31) + 16;      // stage column of pl
        float4 v;
        v.x = sm->stage[(i0 + 4 * q + 3) & 31][sa];
        v.y = sm->stage[(i0 + 4 * q + 2) & 31][sa];
        v.z = sm->stage[(i0 + 4 * q + 1) & 31][sa];
        v.w = sm->stage[(i0 + 4 * q + 0) & 31][sa];
        *reinterpret_cast<float4*>(O + (size_t)(rank * OWNC + pl) * NN + cb) = v;
    }
}

// One fused scan pair. SRCIN rows are the sequence; OUT gets u_t at [p][NN-1-t].
template <int COLTAPS>
__global__ void __launch_bounds__(NTH, 1) __cluster_dims__(CLC, 1, 1)
scan_kernel(const float* __restrict__ SRCIN, float* __restrict__ OUT,
            const float* __restrict__ preAw, const float* __restrict__ preAb,
            const float* __restrict__ cAw,   const float* __restrict__ cAb,
            const float* __restrict__ preBw, const float* __restrict__ preBb,
            const float* __restrict__ cBw,   const float* __restrict__ cBb)
{
    extern __shared__ char raw[];
    Smem* sm = reinterpret_cast<Smem*>(raw);
    const int rank  = blockIdx.x & (CLC - 1);
    const int batch = blockIdx.x >> 1;
    const float* SRC = SRCIN + (size_t)batch * NN * TT;
    float* O = OUT + (size_t)batch * NN * TT;

    const int tid = threadIdx.x, w = tid >> 5, lane = tid & 31;
#define TI(k) (COLTAPS ? (5 * (k) + 2) : (10 + (k)))
    float aS[5], aX[5], bS[5], bX[5], pB[5];
    #pragma unroll
    for (int k = 0; k < 5; ++k) {
        aS[k] = cAw[TI(k)];
        aX[k] = cAw[25 + TI(k)];
        bS[k] = cBw[TI(k)];
        bX[k] = cBw[25 + TI(k)];
        pB[k] = preBw[TI(k)];
    }
    const float bA = cAb[0], bB = cBb[0], pBb = preBb[0];

    // geometry
    const int off0 = w * 32 + 2 * lane;          // CTA-window coord of slot 0 (0..542)
    const int g0   = rank * OWNC - HB + off0;    // global position of slot 0
    const bool inD0 = (g0 >= 0) && (g0 < NN);
    const bool inD1 = (g0 + 1 >= 0) && (g0 + 1 < NN);
    const bool own  = (lane >= 8 && lane < 24);
    const bool edgeW = (rank == 0 && w == 0) || (rank == CLC - 1 && w == NWP - 1);
    const bool remL = (rank > 0) && (w == 0) && (lane >= 8 && lane < 16);
    const bool remR = (rank < CLC - 1) && (w == NWP - 1) && (lane >= 16 && lane < 24);
    const int gr = g0 < 0 ? 0 : (g0 > NN - 2 ? NN - 2 : g0);          // float2-safe
    const int ge = (lane == 0) ? g0 - 2 : g0 + 2;                     // edge pair
    const bool inE0 = (ge >= 0) && (ge < NN);
    const bool inE1 = (ge + 1 >= 0) && (ge + 1 < NN);
    const int gec = ge < 0 ? 0 : (ge > NN - 2 ? NN - 2 : ge);
    const int stb = w * 66 + 2 * lane;

    // zero exchange buffers (edge-halo slots stay 0 forever = domain padding)
    {
        float* p0 = &sm->sEx[0][0];
        float* p1 = &sm->uEx[0][0];
        for (int i = tid; i < 2 * EXW; i += NTH) { p0[i] = 0.f; p1[i] = 0.f; }
    }
    __syncthreads();
    CLUSTER_ARRIVE();           // all exchange buffers zeroed cluster-wide
    CLUSTER_WAIT();

    const float2* xb = reinterpret_cast<const float2*>(SRC + gr);
    const float2* eb = reinterpret_cast<const float2*>(SRC + gec);
    const int RS = NN / 2;

    // prologue rows 0..5
    float2 av  = xb[0],      ae  = eb[0];
    float2 bv  = xb[RS],     be  = eb[RS];
    float2 r0v = xb[2 * RS], r0e = eb[2 * RS];
    float2 r1v = xb[3 * RS], r1e = eb[3 * RS];
    float2 r2v = xb[4 * RS], r2e = eb[4 * RS];
    float2 r3v = xb[5 * RS], r3e = eb[5 * RS];

    float s0, s1, u0, u1;

    // ---- t = 0: s_0 = preA(row 0) ----
    {
        float pA[5];
        #pragma unroll
        for (int k = 0; k < 5; ++k) pA[k] = preAw[TI(k)];
        const float pAb = preAb[0];
        if (edgeW) {
            if (!inD0) av.x = 0.f;  if (!inD1) av.y = 0.f;
            if (!inE0) ae.x = 0.f;  if (!inE1) ae.y = 0.f;
        }
        float xL2, xL1, xR0, xR1;
        XHALOE(av, ae, xL2, xL1, xR0, xR1);
        float a0 = pAb, a1 = pAb;
        conv2acc(a0, a1, xL2, xL1, av.x, av.y, xR0, xR1, pA);
        s0 = inD0 ? a0 : 0.f;
        s1 = inD1 ? a1 : 0.f;
    }

    // ---- t = 1: s_1 = convX(row1) + convS(s_0) + bA ; u_0 = preB(s_0) ----
    {
        if (edgeW) {
            if (!inD0) bv.x = 0.f;  if (!inD1) bv.y = 0.f;
            if (!inE0) be.x = 0.f;  if (!inE1) be.y = 0.f;
        }
        float xL2, xL1, xR0, xR1, sL2, sL1, sR0, sR1;
        XHALOE(bv, be, xL2, xL1, xR0, xR1);
        HALO2(s0, s1, sL2, sL1, sR0, sR1);
        float a0 = bA, a1 = bA;
        conv2acc(a0, a1, xL2, xL1, bv.x, bv.y, xR0, xR1, aX);
        conv2acc(a0, a1, sL2, sL1, s0, s1, sR0, sR1, aS);
        float c0 = pBb, c1 = pBb;
        conv2acc(c0, c1, sL2, sL1, s0, s1, sR0, sR1, pB);
        if (edgeW) {
            if (!inD0) { a0 = 0.f; c0 = 0.f; }
            if (!inD1) { a1 = 0.f; c1 = 0.f; }
        }
        s0 = a0; s1 = a1; u0 = c0; u1 = c1;
        *reinterpret_cast<float2*>(&sm->stage[0][stb]) = make_float2(u0, u1);
    }

    // main body: tick t computes s_t and u_{t-1}; consumes ring slot (xv,xe);
    // refills it with clamped row t+4.
    auto body = [&](int t, float2& xv, float2& xe) {
        if (edgeW) {
            if (!inD0) xv.x = 0.f;  if (!inD1) xv.y = 0.f;
            if (!inE0) xe.x = 0.f;  if (!inE1) xe.y = 0.f;
        }
        float xL2, xL1, xR0, xR1, sL2, sL1, sR0, sR1, uL2, uL1, uR0, uR1;
        XHALOE(xv, xe, xL2, xL1, xR0, xR1);
        HALO2(s0, s1, sL2, sL1, sR0, sR1);
        HALO2(u0, u1, uL2, uL1, uR0, uR1);

        float a0 = bA, a1 = bA;
        conv2acc(a0, a1, xL2, xL1, xv.x, xv.y, xR0, xR1, aX);
        conv2acc(a0, a1, sL2, sL1, s0, s1, sR0, sR1, aS);
        float cu0 = bB, cu1 = bB;
        conv2acc(cu0, cu1, uL2, uL1, u0, u1, uR0, uR1, bS);
        float cs0 = 0.f, cs1 = 0.f;
        conv2acc(cs0, cs1, sL2, sL1, s0, s1, sR0, sR1, bX);
        float c0 = cu0 + cs0, c1 = cu1 + cs1;

        if (edgeW) {
            if (!inD0) { a0 = 0.f; c0 = 0.f; }
            if (!inD1) { a1 = 0.f; c1 = 0.f; }
        }
        const int sr = (t - 1) & 31;
        *reinterpret_cast<float2*>(&sm->stage[sr][stb]) = make_float2(c0, c1);
        s0 = a0; s1 = a1; u0 = c0; u1 = c1;

        // clamped depth-4 prefetch
        int pr = t + 4; pr = pr > TT - 1 ? TT - 1 : pr;
        xv = xb[(size_t)pr * RS];
        xe = eb[(size_t)pr * RS];

        if ((t & 7) == 0) {                       // exchange epoch
            const int buf = (t >> 3) & 1;
            if (own) {
                *reinterpret_cast<float2*>(&sm->sEx[buf][off0]) = make_float2(s0, s1);
                *reinterpret_cast<float2*>(&sm->uEx[buf][off0]) = make_float2(u0, u1);
            }
            if (remL) {
                dsm_store2(&sm->sEx[buf][off0 + OWNC], rank - 1, s0, s1);
                dsm_store2(&sm->uEx[buf][off0 + OWNC], rank - 1, u0, u1);
            }
            if (remR) {
                dsm_store2(&sm->sEx[buf][off0 - OWNC], rank + 1, s0, s1);
                dsm_store2(&sm->uEx[buf][off0 - OWNC], rank + 1, u0, u1);
            }
            __syncthreads();
            CLUSTER_ARRIVE();
            if ((t & 15) == 0) flush16(sm, O, t - 16, tid, rank);  // overlap with wait
            CLUSTER_WAIT();
            if (!own) {
                if (inD0) {
                    float2 sv = *reinterpret_cast<const float2*>(&sm->sEx[buf][off0]);
                    float2 uv = *reinterpret_cast<const float2*>(&sm->uEx[buf][off0]);
                    s0 = sv.x; u0 = uv.x;
                    if (inD1) { s1 = sv.y; u1 = uv.y; }
                } else if (inD1) {
                    s1 = sm->sEx[buf][off0 + 1]; u1 = sm->uEx[buf][off0 + 1];
                }
            }
        }
    };

    // t = 2 .. 1021 in x4 groups, then 1022, 1023
    #pragma unroll 1
    for (int t = 2; t <= TT - 6; t += 4) {
        body(t,     r0v, r0e);
        body(t + 1, r1v, r1e);
        body(t + 2, r2v, r2e);
        body(t + 3, r3v, r3e);
    }
    body(TT - 2, r0v, r0e);
    body(TT - 1, r1v, r1e);

    // epilogue t = TT: u_{TT-1}
    {
        float sL2, sL1, sR0, sR1, uL2, uL1, uR0, uR1;
        HALO2(s0, s1, sL2, sL1, sR0, sR1);
        HALO2(u0, u1, uL2, uL1, uR0, uR1);
        float cu0 = bB, cu1 = bB;
        conv2acc(cu0, cu1, uL2, uL1, u0, u1, uR0, uR1, bS);
        float cs0 = 0.f, cs1 = 0.f;
        conv2acc(cs0, cs1, sL2, sL1, s0, s1, sR0, sR1, bX);
        float c0 = cu0 + cs0, c1 = cu1 + cs1;
        if (edgeW) { if (!inD0) c0 = 0.f; if (!inD1) c1 = 0.f; }
        *reinterpret_cast<float2*>(&sm->stage[31][stb]) = make_float2(c0, c1);
        __syncthreads();
        flush16(sm, O, TT - 16, tid, rank);
    }
#undef TI
}

extern "C" void kernel_launch(void* const* d_in, const int* in_sizes, int n_in,
                              void* d_out, int out_size)
{
    (void)in_sizes; (void)n_in; (void)out_size;
    const float* x   = (const float*)d_in[0];
    const float* p1w = (const float*)d_in[1];
    const float* p1b = (const float*)d_in[2];
    const float* p2w = (const float*)d_in[3];
    const float* p2b = (const float*)d_in[4];
    const float* p3w = (const float*)d_in[5];
    const float* p3b = (const float*)d_in[6];
    const float* p4w = (const float*)d_in[7];
    const float* p4b = (const float*)d_in[8];
    const float* c1w = (const float*)d_in[9];
    const float* c1b = (const float*)d_in[10];
    const float* c2w = (const float*)d_in[11];
    const float* c2b = (const float*)d_in[12];
    const float* c3w = (const float*)d_in[13];
    const float* c3b = (const float*)d_in[14];
    const float* c4w = (const float*)d_in[15];
    const float* c4b = (const float*)d_in[16];

    float* scr = nullptr;
    cudaGetSymbolAddress((void**)&scr, g_scr);

    cudaFuncSetAttribute(scan_kernel<0>, cudaFuncAttributeMaxDynamicSharedMemorySize, (int)sizeof(Smem));
    cudaFuncSetAttribute(scan_kernel<1>, cudaFuncAttributeMaxDynamicSharedMemorySize, (int)sizeof(Smem));

    // phase A: passes 1+2 (scan over h, row taps): x -> g_scr (transposed+reversed)
    scan_kernel<0><<<8 * CLC, NTH, sizeof(Smem)>>>(
        x, scr, p1w, p1b, c1w, c1b, p2w, p2b, c2w, c2b);
    // phase B: passes 3+4 (scan over w, col taps): g_scr -> out
    scan_kernel<1><<<8 * CLC, NTH, sizeof(Smem)>>>(
        scr, (float*)d_out, p3w, p3b, c3w, c3b, p4w, p4b, c4w, c4b);
}